// round 8
// baseline (speedup 1.0000x reference)
#include <cuda_runtime.h>
#include <cuda_bf16.h>
#include <cstdint>
#include <math_constants.h>

// ---------------------------------------------------------------------------
// AdaptiveEMAModel. Measured-best structure (R7) + ONE structural change:
//  * vocab-table preprocess (FFN/LN/kproj over 32000 rows, 4.1x fewer flops)
//  * fp32 + packed fma.rn.f32x2 (SASS FFMA2)
//  * scan: row-split (2 threads/row), smem kn ring w/ 3-step prefetch,
//    DEFERRED-FIRE: fire_{t-1} is resolved at step t (red written last step),
//    and the s_{t-1} rank-1 update is applied right before the matvec ->
//    bit-identical math, ONE barrier per step, dsq tree off the critical path.
// ---------------------------------------------------------------------------

typedef unsigned long long u64t;

__device__ __forceinline__ u64t pk2(float lo, float hi) {
    u64t r;
    asm("mov.b64 %0, {%1, %2};" : "=l"(r) : "f"(lo), "f"(hi));
    return r;
}
__device__ __forceinline__ void fma2(u64t& d, u64t a, u64t b) {
    asm("fma.rn.f32x2 %0, %1, %2, %0;" : "+l"(d) : "l"(a), "l"(b));
}
__device__ __forceinline__ float2 upk(u64t v) {
    float2 f;
    asm("mov.b64 {%0, %1}, %2;" : "=f"(f.x), "=f"(f.y) : "l"(v));
    return f;
}
__device__ __forceinline__ float hsum(u64t v) {
    float2 f = upk(v);
    return f.x + f.y;
}

#define Bn   64
#define Ln   2048
#define Hn   128
#define H2n  256
#define Vn   32000
#define NTOK (Bn * Ln)

// ------------------------- global scratch ----------------------------------
__device__ __align__(16) float g_y[(size_t)Vn * H2n];      // 32.8 MB
__device__ __align__(16) float g_hln[(size_t)Vn * Hn];     // 16.4 MB
__device__ __align__(16) float g_Kv[(size_t)Vn * Hn];      // raw k per vocab
__device__ __align__(16) float g_KNv[(size_t)Vn * Hn];     // normalized k
__device__ __align__(16) float g_THv[Vn];                  // (0.4*||k||)^2
__device__ __align__(16) float g_knall[(size_t)NTOK * Hn]; // per-token kn
__device__ __align__(16) float g_read[Bn * Hn];
__device__ __align__(16) float g_r2[Bn * Hn];
__device__ int g_is64;

// ------------------------- K0: detect seq dtype ----------------------------
__global__ void k0_detect(const unsigned int* __restrict__ sw) {
    int t = threadIdx.x;
    int nz = (sw[2 * t + 1] != 0u) ? 1 : 0;
    nz = __syncthreads_or(nz);
    if (t == 0) g_is64 = nz ? 0 : 1;
}

// ------------------------- KV1: FFN layer 1 over vocab ---------------------
#define KV1_SMEM ((256 * 132 + 32 * 132) * 4)

__global__ __launch_bounds__(256, 1)
void kv1(const float* __restrict__ ew,
         const float* __restrict__ w1, const float* __restrict__ b1) {
    extern __shared__ float sm[];
    float* W = sm;                // 256 x 132
    float* X = sm + 256 * 132;    // 32 x 132

    const int tid = threadIdx.x;
    const int lane = tid & 31;
    const int w = tid >> 5;
    const int tg = (w & 3) * 8;
    const int ob = (w >> 2) * 4;

    for (int i = tid; i < 256 * 32; i += 256) {
        int r = i >> 5, c = i & 31;
        *(float4*)(W + r * 132 + 4 * c) = *(const float4*)(w1 + r * 128 + 4 * c);
    }
    float bb[4];
#pragma unroll
    for (int j = 0; j < 4; ++j) bb[j] = b1[lane + 32 * (ob + j)];
    __syncthreads();

    const float4* W4 = (const float4*)W;
    const float4* X4 = (const float4*)X;

    for (int tile = blockIdx.x; tile < Vn / 32; tile += gridDim.x) {
        const int v0 = tile * 32;
        for (int i = tid; i < 32 * 32; i += 256) {
            int tk = i >> 5, q = i & 31;
            *(float4*)(X + tk * 132 + 4 * q) = *(const float4*)(ew + (size_t)(v0 + tk) * 128 + 4 * q);
        }
        __syncthreads();

        u64t acc[8][4];
#pragma unroll
        for (int i = 0; i < 8; ++i)
#pragma unroll
            for (int j = 0; j < 4; ++j) acc[i][j] = 0ull;

#pragma unroll 4
        for (int hh = 0; hh < 32; ++hh) {
            u64t wl[4], wh[4];
#pragma unroll
            for (int j = 0; j < 4; ++j) {
                float4 wq = W4[(lane + 32 * (ob + j)) * 33 + hh];
                wl[j] = pk2(wq.x, wq.y);
                wh[j] = pk2(wq.z, wq.w);
            }
#pragma unroll
            for (int i = 0; i < 8; ++i) {
                float4 xq = X4[(tg + i) * 33 + hh];
                u64t xl = pk2(xq.x, xq.y), xh = pk2(xq.z, xq.w);
#pragma unroll
                for (int j = 0; j < 4; ++j) {
                    fma2(acc[i][j], xl, wl[j]);
                    fma2(acc[i][j], xh, wh[j]);
                }
            }
        }
#pragma unroll
        for (int i = 0; i < 8; ++i)
#pragma unroll
            for (int j = 0; j < 4; ++j) {
                float y = hsum(acc[i][j]) + bb[j];
                g_y[(size_t)(v0 + tg + i) * H2n + lane + 32 * (ob + j)] = fmaxf(y, 0.0f);
            }
        __syncthreads();
    }
}

// ------------------------- KV2: FFN layer 2 + residual + LN over vocab -----
#define KV2_SMEM ((128 * 260 + 64 * 260) * 4)

__global__ __launch_bounds__(256, 1)
void kv2(const float* __restrict__ ew,
         const float* __restrict__ w2, const float* __restrict__ b2,
         const float* __restrict__ lng, const float* __restrict__ lnb) {
    extern __shared__ float sm[];
    float* W = sm;                // 128 x 260
    float* Y = sm + 128 * 260;    // 64 x 260

    const int tid = threadIdx.x;
    const int lane = tid & 31;
    const int w = tid >> 5;
    const int tg = w * 8;

    for (int i = tid; i < 128 * 64; i += 256) {
        int r = i >> 6, c = i & 63;
        *(float4*)(W + r * 260 + 4 * c) = *(const float4*)(w2 + r * 256 + 4 * c);
    }
    float b2r[4], gr[4], br[4];
#pragma unroll
    for (int j = 0; j < 4; ++j) {
        b2r[j] = b2[lane + 32 * j];
        gr[j] = lng[lane + 32 * j];
        br[j] = lnb[lane + 32 * j];
    }
    __syncthreads();

    const float4* W4 = (const float4*)W;
    const float4* Y4 = (const float4*)Y;

    for (int tile = blockIdx.x; tile < Vn / 64; tile += gridDim.x) {
        const int v0 = tile * 64;
        for (int i = tid; i < 64 * 64; i += 256) {
            int tk = i >> 6, c = i & 63;
            *(float4*)(Y + tk * 260 + 4 * c) = *(const float4*)(g_y + (size_t)(v0 + tk) * H2n + 4 * c);
        }
        __syncthreads();

        u64t acc[8][4];
#pragma unroll
        for (int i = 0; i < 8; ++i)
#pragma unroll
            for (int j = 0; j < 4; ++j) acc[i][j] = 0ull;

#pragma unroll 2
        for (int oo = 0; oo < 64; ++oo) {
            u64t wl[4], wh[4];
#pragma unroll
            for (int j = 0; j < 4; ++j) {
                float4 wq = W4[(lane + 32 * j) * 65 + oo];
                wl[j] = pk2(wq.x, wq.y);
                wh[j] = pk2(wq.z, wq.w);
            }
#pragma unroll
            for (int i = 0; i < 8; ++i) {
                float4 yq = Y4[(tg + i) * 65 + oo];
                u64t yl = pk2(yq.x, yq.y), yh = pk2(yq.z, yq.w);
#pragma unroll
                for (int j = 0; j < 4; ++j) {
                    fma2(acc[i][j], yl, wl[j]);
                    fma2(acc[i][j], yh, wh[j]);
                }
            }
        }

#pragma unroll
        for (int i = 0; i < 8; ++i) {
            const size_t tok = (size_t)(v0 + tg + i);
            float x[4];
#pragma unroll
            for (int j = 0; j < 4; ++j)
                x[j] = hsum(acc[i][j]) + b2r[j] + ew[tok * 128 + lane + 32 * j];
            float s = x[0] + x[1] + x[2] + x[3];
#pragma unroll
            for (int off = 16; off; off >>= 1) s += __shfl_xor_sync(0xffffffffu, s, off);
            float mu = s * (1.0f / 128.0f);
            float vs = 0.0f;
#pragma unroll
            for (int j = 0; j < 4; ++j) { float dv = x[j] - mu; vs += dv * dv; }
#pragma unroll
            for (int off = 16; off; off >>= 1) vs += __shfl_xor_sync(0xffffffffu, vs, off);
            float den = sqrtf(vs * (1.0f / 128.0f) + 1e-5f);
#pragma unroll
            for (int j = 0; j < 4; ++j)
                g_hln[tok * Hn + lane + 32 * j] = (x[j] - mu) / den * gr[j] + br[j];
        }
        __syncthreads();
    }
}

// ------------------------- KV3: kproj + norm/kn/threshold over vocab -------
#define KV3_SMEM ((128 * 132 + 64 * 132) * 4)

__global__ __launch_bounds__(256, 1)
void kv3(const float* __restrict__ kpw) {
    extern __shared__ float sm[];
    float* W = sm;                // 128 x 132
    float* X = sm + 128 * 132;    // 64 x 132

    const int tid = threadIdx.x;
    const int lane = tid & 31;
    const int w = tid >> 5;
    const int tg = w * 8;

    for (int i = tid; i < 128 * 32; i += 256) {
        int r = i >> 5, c = i & 31;
        *(float4*)(W + r * 132 + 4 * c) = *(const float4*)(kpw + r * 128 + 4 * c);
    }
    __syncthreads();

    const float4* W4 = (const float4*)W;
    const float4* X4 = (const float4*)X;

    for (int tile = blockIdx.x; tile < Vn / 64; tile += gridDim.x) {
        const int v0 = tile * 64;
        for (int i = tid; i < 64 * 32; i += 256) {
            int tk = i >> 5, q = i & 31;
            *(float4*)(X + tk * 132 + 4 * q) = *(const float4*)(g_hln + (size_t)(v0 + tk) * Hn + 4 * q);
        }
        __syncthreads();

        u64t acc[8][4];
#pragma unroll
        for (int i = 0; i < 8; ++i)
#pragma unroll
            for (int j = 0; j < 4; ++j) acc[i][j] = 0ull;

#pragma unroll 4
        for (int hh = 0; hh < 32; ++hh) {
            u64t wl[4], wh[4];
#pragma unroll
            for (int j = 0; j < 4; ++j) {
                float4 wq = W4[(lane + 32 * j) * 33 + hh];
                wl[j] = pk2(wq.x, wq.y);
                wh[j] = pk2(wq.z, wq.w);
            }
#pragma unroll
            for (int i = 0; i < 8; ++i) {
                float4 xq = X4[(tg + i) * 33 + hh];
                u64t xl = pk2(xq.x, xq.y), xh = pk2(xq.z, xq.w);
#pragma unroll
                for (int j = 0; j < 4; ++j) {
                    fma2(acc[i][j], xl, wl[j]);
                    fma2(acc[i][j], xh, wh[j]);
                }
            }
        }
#pragma unroll
        for (int i = 0; i < 8; ++i) {
            const size_t tok = (size_t)(v0 + tg + i);
            float kv[4];
            float s = 0.0f;
#pragma unroll
            for (int j = 0; j < 4; ++j) {
                kv[j] = hsum(acc[i][j]);
                g_Kv[tok * Hn + lane + 32 * j] = kv[j];
                s += kv[j] * kv[j];
            }
#pragma unroll
            for (int off = 16; off; off >>= 1) s += __shfl_xor_sync(0xffffffffu, s, off);
            float nm = fmaxf(sqrtf(s), 1e-12f);
#pragma unroll
            for (int j = 0; j < 4; ++j)
                g_KNv[tok * Hn + lane + 32 * j] = kv[j] / nm;
            if (lane == 0) {
                float t1 = 0.4f * nm;
                g_THv[tok] = t1 * t1;
            }
        }
        __syncthreads();
    }
}

// ------------------------- KG: gather kn per token -------------------------
__global__ void kg(const void* __restrict__ seq) {
    const int lane = threadIdx.x & 31;
    const int w = threadIdx.x >> 5;
    const size_t gt = (size_t)blockIdx.x * 8 + w;
    const int is64 = g_is64;
    const long long i1 = is64 ? ((const long long*)seq)[gt]
                              : (long long)((const int*)seq)[gt];
    ((float4*)g_knall)[gt * 32 + lane] = ((const float4*)g_KNv)[(size_t)i1 * 32 + lane];
}

// ------------------------- K2: deferred-fire delta-rule scan ---------------
// 64 CTAs x 256 threads. Thread pair (2r, 2r+1) owns M row r (64 cols each
// as 32 f32x2 regs). ONE barrier per step: fire_{t-1} resolved at step t from
// the red buffer written last step; the s_{t-1} update is applied right
// before the matvec (kn_{t-1} kept in registers) -> exact same arithmetic.
__global__ __launch_bounds__(256, 1)
void k2_scan(const void* __restrict__ seq) {
    const int b = blockIdx.x;
    const int tid = threadIdx.x;
    const int lane = tid & 31;
    const int w = tid >> 5;
    const int row = tid >> 1;
    const int half = tid & 1;

    __shared__ int   idxs[Ln];
    __shared__ float ths[Ln];
    __shared__ __align__(16) float kns[8][136];   // kn ring, slot = t & 7
    __shared__ __align__(16) float red[2][8];

    const int is64 = g_is64;
    for (int i = tid; i < Ln; i += 256) {
        long long idx = is64 ? ((const long long*)seq)[(size_t)b * Ln + i]
                             : (long long)((const int*)seq)[(size_t)b * Ln + i];
        idxs[i] = (int)idx;
        ths[i] = g_THv[idx];
    }
    if (tid < 16) red[tid >> 3][tid & 7] = 0.0f;

    const float* KNb = g_knall + (size_t)b * Ln * Hn;

    // kn ring layout: value for column j at kns[buf][68*(j>>6) + (j&63)]
    const int pos = 68 * (row >> 6) + (row & 63);
    if (half == 0) {
        kns[0][pos] = KNb[row];
        kns[1][pos] = KNb[Hn + row];
    }
    float Lprev = KNb[2 * Hn + row];                       // kn[2] in flight
    float kcur = g_Kv[(size_t)idxs[0] * Hn + row];         // k_t (own row)
    float knx1 = g_Kv[(size_t)idxs[1] * Hn + row];
    float knx2 = g_Kv[(size_t)idxs[2] * Hn + row];

    u64t M[32];
    u64t krP[32];                                          // kn_{t-1} regs
#pragma unroll
    for (int c = 0; c < 32; ++c) { M[c] = 0ull; krP[c] = 0ull; }

    float dprev = 0.0f;
    float thprev = CUDART_INF_F;                           // fire_{-1} = 0

#pragma unroll 2
    for (int t = 0; t < Ln - 1; ++t) {
        __syncthreads();   // red[t-1] + ring slot t visible

        // ---- resolve fire_{t-1}; s1 = fire * d_{t-1,row} / 2048 ----
        float4 r0 = *(const float4*)&red[(t + 1) & 1][0];
        float4 r1 = *(const float4*)&red[(t + 1) & 1][4];
        float dd = ((r0.x + r0.y) + (r0.z + r0.w)) + ((r1.x + r1.y) + (r1.z + r1.w));
        float f = (dd >= thprev) ? (1.0f / 2048.0f) : 0.0f;
        float s1 = dprev * f;
        u64t s1p = pk2(s1, s1);

        // ---- fused: M += s1 * kn_{t-1} (regs); acc = M . kn_t (ring) ----
        const float4* knT4 = (const float4*)(kns[t & 7] + 68 * half);
        u64t a0 = 0ull, a1 = 0ull;
#pragma unroll
        for (int cc = 0; cc < 16; ++cc) {
            float4 v = knT4[cc];
            u64t c0 = pk2(v.x, v.y);
            u64t c1 = pk2(v.z, v.w);
            fma2(M[2 * cc], s1p, krP[2 * cc]);
            fma2(M[2 * cc + 1], s1p, krP[2 * cc + 1]);
            fma2(a0, M[2 * cc], c0);
            fma2(a1, M[2 * cc + 1], c1);
            krP[2 * cc] = c0;
            krP[2 * cc + 1] = c1;
        }
        float vph = hsum(a0) + hsum(a1);
        float vp = vph + __shfl_xor_sync(0xffffffffu, vph, 1);
        float d = kcur - vp;

        // ---- ||d||^2 tree + STS (consumed NEXT step: off critical path) ----
        float dsq = d * d;
        dsq += __shfl_xor_sync(0xffffffffu, dsq, 2);
        dsq += __shfl_xor_sync(0xffffffffu, dsq, 4);
        dsq += __shfl_xor_sync(0xffffffffu, dsq, 8);
        dsq += __shfl_xor_sync(0xffffffffu, dsq, 16);
        if (lane == 0) red[t & 1][w] = dsq;

        // ---- ring store kn[t+2] (loaded 2 iters ago) ----
        if (half == 0) kns[(t + 2) & 7][pos] = Lprev;

        // ---- global prefetches (3 steps ahead) ----
        const int tp = t + 3;
        float Lnew = 0.0f;
        if (tp < Ln - 1)       Lnew = KNb[(size_t)tp * Hn + row];
        else if (tp == Ln - 1) Lnew = g_Kv[(size_t)idxs[Ln - 1] * Hn + row];  // raw q
        const int tk = (tp < Ln) ? tp : Ln - 1;
        float knew = g_Kv[(size_t)idxs[tk] * Hn + row];

        dprev = d;
        thprev = ths[t];
        kcur = knx1; knx1 = knx2; knx2 = knew;
        Lprev = Lnew;
    }

    // ---- finalize: fire_{2046} update, then read = M @ q ----
    __syncthreads();
    {
        float4 r0 = *(const float4*)&red[(Ln - 2) & 1][0];
        float4 r1 = *(const float4*)&red[(Ln - 2) & 1][4];
        float dd = ((r0.x + r0.y) + (r0.z + r0.w)) + ((r1.x + r1.y) + (r1.z + r1.w));
        float f = (dd >= thprev) ? (1.0f / 2048.0f) : 0.0f;
        float s1 = dprev * f;
        u64t s1p = pk2(s1, s1);

        const float4* q4 = (const float4*)(kns[(Ln - 1) & 7] + 68 * half);
        u64t a0 = 0ull, a1 = 0ull;
#pragma unroll
        for (int cc = 0; cc < 16; ++cc) {
            float4 v = q4[cc];
            fma2(M[2 * cc], s1p, krP[2 * cc]);        // krP = kn_{2046}
            fma2(M[2 * cc + 1], s1p, krP[2 * cc + 1]);
            fma2(a0, M[2 * cc], pk2(v.x, v.y));
            fma2(a1, M[2 * cc + 1], pk2(v.z, v.w));
        }
        float vph = hsum(a0) + hsum(a1);
        float rd = vph + __shfl_xor_sync(0xffffffffu, vph, 1);
        if (half == 0) g_read[b * Hn + row] = rd;
    }
}

// ------------------------- K2b: r2 = read @ rp_w^T + rp_b ------------------
__global__ void k2b(const float* __restrict__ rpw, const float* __restrict__ rpb) {
    __shared__ __align__(16) float rs[128];
    const int b = blockIdx.x, tid = threadIdx.x;
    rs[tid] = g_read[b * Hn + tid];
    __syncthreads();
    const u64t* rp = (const u64t*)rs;
    u64t acc = 0ull;
#pragma unroll 8
    for (int j2 = 0; j2 < 64; ++j2) {
        u64t wv = *(const u64t*)(rpw + tid * 128 + 2 * j2);
        fma2(acc, rp[j2], wv);
    }
    g_r2[b * Hn + tid] = hsum(acc) + rpb[tid];
}

// ------------------------- K3: out = r2 @ out_w^T + out_b ------------------
#define K3_SMEM ((64 * 128 + 64 * 130) * 4)

__global__ __launch_bounds__(256, 1)
void k3(const float* __restrict__ ow, const float* __restrict__ ob,
        float* __restrict__ out) {
    extern __shared__ float sm[];
    float* r2s = sm;             // 64 x 128
    float* ws = sm + 64 * 128;   // 64 x 130

    const int tid = threadIdx.x;
    const int v0 = blockIdx.x * 64;

    for (int i = tid; i < 64 * 32; i += 256)
        ((float4*)r2s)[i] = ((const float4*)g_r2)[i];
    for (int i = tid; i < 64 * 64; i += 256) {
        int r = i >> 6, c = i & 63;
        *(float2*)(ws + r * 130 + 2 * c) = *(const float2*)(ow + (size_t)(v0 + r) * 128 + 2 * c);
    }
    __syncthreads();

    const int vl = tid & 63;
    const int bg = tid >> 6;
    const float obv = ob[v0 + vl];

#pragma unroll 4
    for (int bi = 0; bi < 16; ++bi) {
        int bb = bg * 16 + bi;
        u64t acc = 0ull;
#pragma unroll 16
        for (int h2 = 0; h2 < 64; ++h2)
            fma2(acc, *(const u64t*)(r2s + bb * 128 + 2 * h2),
                      *(const u64t*)(ws + vl * 130 + 2 * h2));
        out[(size_t)bb * Vn + v0 + vl] = hsum(acc) + obv;
    }
}

// ------------------------- launch ------------------------------------------
extern "C" void kernel_launch(void* const* d_in, const int* in_sizes, int n_in,
                              void* d_out, int out_size) {
    (void)in_sizes; (void)n_in; (void)out_size;
    const void*  seq = d_in[0];
    const float* ew  = (const float*)d_in[1];
    const float* w1  = (const float*)d_in[2];
    const float* b1  = (const float*)d_in[3];
    const float* w2  = (const float*)d_in[4];
    const float* b2  = (const float*)d_in[5];
    const float* lng = (const float*)d_in[6];
    const float* lnb = (const float*)d_in[7];
    const float* kpw = (const float*)d_in[8];
    const float* rpw = (const float*)d_in[9];
    const float* rpb = (const float*)d_in[10];
    const float* ow  = (const float*)d_in[11];
    const float* ob  = (const float*)d_in[12];
    float* out = (float*)d_out;

    cudaFuncSetAttribute(kv1, cudaFuncAttributeMaxDynamicSharedMemorySize, KV1_SMEM);
    cudaFuncSetAttribute(kv2, cudaFuncAttributeMaxDynamicSharedMemorySize, KV2_SMEM);
    cudaFuncSetAttribute(kv3, cudaFuncAttributeMaxDynamicSharedMemorySize, KV3_SMEM);
    cudaFuncSetAttribute(k3,  cudaFuncAttributeMaxDynamicSharedMemorySize, K3_SMEM);

    k0_detect<<<1, 256>>>((const unsigned int*)seq);
    kv1<<<148, 256, KV1_SMEM>>>(ew, w1, b1);
    kv2<<<148, 256, KV2_SMEM>>>(ew, w2, b2, lng, lnb);
    kv3<<<296, 256, KV3_SMEM>>>(kpw);
    kg <<<NTOK / 8, 256>>>(seq);
    k2_scan<<<Bn, 256>>>(seq);
    k2b<<<Bn, 128>>>(rpw, rpb);
    k3<<<Vn / 64, 256, K3_SMEM>>>(ow, ob, out);
}

// round 9
// speedup vs baseline: 1.1925x; 1.1925x over previous
#include <cuda_runtime.h>
#include <cuda_bf16.h>
#include <cstdint>

// ---------------------------------------------------------------------------
// AdaptiveEMAModel. Measured-best scan structure (R7) with:
//  * ONE barrier per step (ring/red double-buffer hazard audit allows it)
//  * kn + raw k + threshold all read from L2-hot vocab tables through the
//    smem idx list (kg gather kernel deleted)
//  * vocab-table preprocess (FFN/LN/kproj over 32000 rows)
//  * fp32 + packed fma.rn.f32x2 (SASS FFMA2)
// ---------------------------------------------------------------------------

typedef unsigned long long u64t;

__device__ __forceinline__ u64t pk2(float lo, float hi) {
    u64t r;
    asm("mov.b64 %0, {%1, %2};" : "=l"(r) : "f"(lo), "f"(hi));
    return r;
}
__device__ __forceinline__ void fma2(u64t& d, u64t a, u64t b) {
    asm("fma.rn.f32x2 %0, %1, %2, %0;" : "+l"(d) : "l"(a), "l"(b));
}
__device__ __forceinline__ float2 upk(u64t v) {
    float2 f;
    asm("mov.b64 {%0, %1}, %2;" : "=f"(f.x), "=f"(f.y) : "l"(v));
    return f;
}
__device__ __forceinline__ float hsum(u64t v) {
    float2 f = upk(v);
    return f.x + f.y;
}

#define Bn   64
#define Ln   2048
#define Hn   128
#define H2n  256
#define Vn   32000
#define NTOK (Bn * Ln)

// ------------------------- global scratch ----------------------------------
__device__ __align__(16) float g_y[(size_t)Vn * H2n];      // 32.8 MB
__device__ __align__(16) float g_hln[(size_t)Vn * Hn];     // 16.4 MB
__device__ __align__(16) float g_Kv[(size_t)Vn * Hn];      // raw k per vocab
__device__ __align__(16) float g_KNv[(size_t)Vn * Hn];     // normalized k
__device__ __align__(16) float g_THv[Vn];                  // (0.4*||k||)^2
__device__ __align__(16) float g_read[Bn * Hn];
__device__ __align__(16) float g_r2[Bn * Hn];
__device__ int g_is64;

// ------------------------- K0: detect seq dtype ----------------------------
__global__ void k0_detect(const unsigned int* __restrict__ sw) {
    int t = threadIdx.x;
    int nz = (sw[2 * t + 1] != 0u) ? 1 : 0;
    nz = __syncthreads_or(nz);
    if (t == 0) g_is64 = nz ? 0 : 1;
}

// ------------------------- KV1: FFN layer 1 over vocab ---------------------
#define KV1_SMEM ((256 * 132 + 32 * 132) * 4)

__global__ __launch_bounds__(256, 1)
void kv1(const float* __restrict__ ew,
         const float* __restrict__ w1, const float* __restrict__ b1) {
    extern __shared__ float sm[];
    float* W = sm;                // 256 x 132
    float* X = sm + 256 * 132;    // 32 x 132

    const int tid = threadIdx.x;
    const int lane = tid & 31;
    const int w = tid >> 5;
    const int tg = (w & 3) * 8;
    const int ob = (w >> 2) * 4;

    for (int i = tid; i < 256 * 32; i += 256) {
        int r = i >> 5, c = i & 31;
        *(float4*)(W + r * 132 + 4 * c) = *(const float4*)(w1 + r * 128 + 4 * c);
    }
    float bb[4];
#pragma unroll
    for (int j = 0; j < 4; ++j) bb[j] = b1[lane + 32 * (ob + j)];
    __syncthreads();

    const float4* W4 = (const float4*)W;
    const float4* X4 = (const float4*)X;

    for (int tile = blockIdx.x; tile < Vn / 32; tile += gridDim.x) {
        const int v0 = tile * 32;
        for (int i = tid; i < 32 * 32; i += 256) {
            int tk = i >> 5, q = i & 31;
            *(float4*)(X + tk * 132 + 4 * q) = *(const float4*)(ew + (size_t)(v0 + tk) * 128 + 4 * q);
        }
        __syncthreads();

        u64t acc[8][4];
#pragma unroll
        for (int i = 0; i < 8; ++i)
#pragma unroll
            for (int j = 0; j < 4; ++j) acc[i][j] = 0ull;

#pragma unroll 4
        for (int hh = 0; hh < 32; ++hh) {
            u64t wl[4], wh[4];
#pragma unroll
            for (int j = 0; j < 4; ++j) {
                float4 wq = W4[(lane + 32 * (ob + j)) * 33 + hh];
                wl[j] = pk2(wq.x, wq.y);
                wh[j] = pk2(wq.z, wq.w);
            }
#pragma unroll
            for (int i = 0; i < 8; ++i) {
                float4 xq = X4[(tg + i) * 33 + hh];
                u64t xl = pk2(xq.x, xq.y), xh = pk2(xq.z, xq.w);
#pragma unroll
                for (int j = 0; j < 4; ++j) {
                    fma2(acc[i][j], xl, wl[j]);
                    fma2(acc[i][j], xh, wh[j]);
                }
            }
        }
#pragma unroll
        for (int i = 0; i < 8; ++i)
#pragma unroll
            for (int j = 0; j < 4; ++j) {
                float y = hsum(acc[i][j]) + bb[j];
                g_y[(size_t)(v0 + tg + i) * H2n + lane + 32 * (ob + j)] = fmaxf(y, 0.0f);
            }
        __syncthreads();
    }
}

// ------------------------- KV2: FFN layer 2 + residual + LN over vocab -----
#define KV2_SMEM ((128 * 260 + 64 * 260) * 4)

__global__ __launch_bounds__(256, 1)
void kv2(const float* __restrict__ ew,
         const float* __restrict__ w2, const float* __restrict__ b2,
         const float* __restrict__ lng, const float* __restrict__ lnb) {
    extern __shared__ float sm[];
    float* W = sm;                // 128 x 260
    float* Y = sm + 128 * 260;    // 64 x 260

    const int tid = threadIdx.x;
    const int lane = tid & 31;
    const int w = tid >> 5;
    const int tg = w * 8;

    for (int i = tid; i < 128 * 64; i += 256) {
        int r = i >> 6, c = i & 63;
        *(float4*)(W + r * 260 + 4 * c) = *(const float4*)(w2 + r * 256 + 4 * c);
    }
    float b2r[4], gr[4], br[4];
#pragma unroll
    for (int j = 0; j < 4; ++j) {
        b2r[j] = b2[lane + 32 * j];
        gr[j] = lng[lane + 32 * j];
        br[j] = lnb[lane + 32 * j];
    }
    __syncthreads();

    const float4* W4 = (const float4*)W;
    const float4* Y4 = (const float4*)Y;

    for (int tile = blockIdx.x; tile < Vn / 64; tile += gridDim.x) {
        const int v0 = tile * 64;
        for (int i = tid; i < 64 * 64; i += 256) {
            int tk = i >> 6, c = i & 63;
            *(float4*)(Y + tk * 260 + 4 * c) = *(const float4*)(g_y + (size_t)(v0 + tk) * H2n + 4 * c);
        }
        __syncthreads();

        u64t acc[8][4];
#pragma unroll
        for (int i = 0; i < 8; ++i)
#pragma unroll
            for (int j = 0; j < 4; ++j) acc[i][j] = 0ull;

#pragma unroll 2
        for (int oo = 0; oo < 64; ++oo) {
            u64t wl[4], wh[4];
#pragma unroll
            for (int j = 0; j < 4; ++j) {
                float4 wq = W4[(lane + 32 * j) * 65 + oo];
                wl[j] = pk2(wq.x, wq.y);
                wh[j] = pk2(wq.z, wq.w);
            }
#pragma unroll
            for (int i = 0; i < 8; ++i) {
                float4 yq = Y4[(tg + i) * 65 + oo];
                u64t yl = pk2(yq.x, yq.y), yh = pk2(yq.z, yq.w);
#pragma unroll
                for (int j = 0; j < 4; ++j) {
                    fma2(acc[i][j], yl, wl[j]);
                    fma2(acc[i][j], yh, wh[j]);
                }
            }
        }

#pragma unroll
        for (int i = 0; i < 8; ++i) {
            const size_t tok = (size_t)(v0 + tg + i);
            float x[4];
#pragma unroll
            for (int j = 0; j < 4; ++j)
                x[j] = hsum(acc[i][j]) + b2r[j] + ew[tok * 128 + lane + 32 * j];
            float s = x[0] + x[1] + x[2] + x[3];
#pragma unroll
            for (int off = 16; off; off >>= 1) s += __shfl_xor_sync(0xffffffffu, s, off);
            float mu = s * (1.0f / 128.0f);
            float vs = 0.0f;
#pragma unroll
            for (int j = 0; j < 4; ++j) { float dv = x[j] - mu; vs += dv * dv; }
#pragma unroll
            for (int off = 16; off; off >>= 1) vs += __shfl_xor_sync(0xffffffffu, vs, off);
            float den = sqrtf(vs * (1.0f / 128.0f) + 1e-5f);
#pragma unroll
            for (int j = 0; j < 4; ++j)
                g_hln[tok * Hn + lane + 32 * j] = (x[j] - mu) / den * gr[j] + br[j];
        }
        __syncthreads();
    }
}

// ------------------------- KV3: kproj + norm/kn/threshold over vocab -------
#define KV3_SMEM ((128 * 132 + 64 * 132) * 4)

__global__ __launch_bounds__(256, 1)
void kv3(const float* __restrict__ kpw) {
    extern __shared__ float sm[];
    float* W = sm;                // 128 x 132
    float* X = sm + 128 * 132;    // 64 x 132

    const int tid = threadIdx.x;
    const int lane = tid & 31;
    const int w = tid >> 5;
    const int tg = w * 8;

    for (int i = tid; i < 128 * 32; i += 256) {
        int r = i >> 5, c = i & 31;
        *(float4*)(W + r * 132 + 4 * c) = *(const float4*)(kpw + r * 128 + 4 * c);
    }
    __syncthreads();

    const float4* W4 = (const float4*)W;
    const float4* X4 = (const float4*)X;

    for (int tile = blockIdx.x; tile < Vn / 64; tile += gridDim.x) {
        const int v0 = tile * 64;
        for (int i = tid; i < 64 * 32; i += 256) {
            int tk = i >> 5, q = i & 31;
            *(float4*)(X + tk * 132 + 4 * q) = *(const float4*)(g_hln + (size_t)(v0 + tk) * Hn + 4 * q);
        }
        __syncthreads();

        u64t acc[8][4];
#pragma unroll
        for (int i = 0; i < 8; ++i)
#pragma unroll
            for (int j = 0; j < 4; ++j) acc[i][j] = 0ull;

#pragma unroll 4
        for (int hh = 0; hh < 32; ++hh) {
            u64t wl[4], wh[4];
#pragma unroll
            for (int j = 0; j < 4; ++j) {
                float4 wq = W4[(lane + 32 * j) * 33 + hh];
                wl[j] = pk2(wq.x, wq.y);
                wh[j] = pk2(wq.z, wq.w);
            }
#pragma unroll
            for (int i = 0; i < 8; ++i) {
                float4 xq = X4[(tg + i) * 33 + hh];
                u64t xl = pk2(xq.x, xq.y), xh = pk2(xq.z, xq.w);
#pragma unroll
                for (int j = 0; j < 4; ++j) {
                    fma2(acc[i][j], xl, wl[j]);
                    fma2(acc[i][j], xh, wh[j]);
                }
            }
        }
#pragma unroll
        for (int i = 0; i < 8; ++i) {
            const size_t tok = (size_t)(v0 + tg + i);
            float kv[4];
            float s = 0.0f;
#pragma unroll
            for (int j = 0; j < 4; ++j) {
                kv[j] = hsum(acc[i][j]);
                g_Kv[tok * Hn + lane + 32 * j] = kv[j];
                s += kv[j] * kv[j];
            }
#pragma unroll
            for (int off = 16; off; off >>= 1) s += __shfl_xor_sync(0xffffffffu, s, off);
            float nm = fmaxf(sqrtf(s), 1e-12f);
#pragma unroll
            for (int j = 0; j < 4; ++j)
                g_KNv[tok * Hn + lane + 32 * j] = kv[j] / nm;
            if (lane == 0) {
                float t1 = 0.4f * nm;
                g_THv[tok] = t1 * t1;
            }
        }
        __syncthreads();
    }
}

// ------------------------- K2: delta-rule scan (R7 order, single bar) ------
// 64 CTAs x 256 threads. Thread pair (2r, 2r+1) owns M row r (64 cols each
// as 32 f32x2 regs). kn ring in smem written 2 steps ahead (3-step prefetch
// from the L2-hot g_KNv table); raw k + threshold via smem idx -> tables.
// ONE __syncthreads per step: with max warp skew 1, ring slots (>=2 apart)
// and the 2-deep red buffer have no cross-warp hazards.
__global__ __launch_bounds__(256, 1)
void k2_scan(const void* __restrict__ seq) {
    const int b = blockIdx.x;
    const int tid = threadIdx.x;
    const int lane = tid & 31;
    const int w = tid >> 5;
    const int row = tid >> 1;
    const int half = tid & 1;

    __shared__ int   idxs[Ln];
    __shared__ float ths[Ln];
    __shared__ __align__(16) float kns[8][136];   // kn ring, slot = t & 7
    __shared__ __align__(16) float red[2][8];

    const int is64 = g_is64;
    for (int i = tid; i < Ln; i += 256) {
        long long idx = is64 ? ((const long long*)seq)[(size_t)b * Ln + i]
                             : (long long)((const int*)seq)[(size_t)b * Ln + i];
        idxs[i] = (int)idx;
        ths[i] = g_THv[idx];
    }
    __syncthreads();

    // kn ring layout: value for column j at kns[buf][68*(j>>6) + (j&63)]
    const int pos = 68 * (row >> 6) + (row & 63);
    if (half == 0) {
        kns[0][pos] = g_KNv[(size_t)idxs[0] * Hn + row];
        kns[1][pos] = g_KNv[(size_t)idxs[1] * Hn + row];
    }
    float Lprev = g_KNv[(size_t)idxs[2] * Hn + row];       // kn[2] in flight
    float kcur = g_Kv[(size_t)idxs[0] * Hn + row];         // k_t (own row)
    float knx1 = g_Kv[(size_t)idxs[1] * Hn + row];
    float knx2 = g_Kv[(size_t)idxs[2] * Hn + row];
    float thc  = ths[0];

    u64t M[32];
#pragma unroll
    for (int c = 0; c < 32; ++c) M[c] = 0ull;
    __syncthreads();

    for (int t = 0; t < Ln - 1; ++t) {
        // ---- global prefetches (3 steps ahead, L2-hot tables) ----
        const int tp = t + 3;
        float Lnew = 0.0f;
        if (tp < Ln - 1)       Lnew = g_KNv[(size_t)idxs[tp] * Hn + row];
        else if (tp == Ln - 1) Lnew = g_Kv[(size_t)idxs[Ln - 1] * Hn + row];  // raw q
        const int tk = (tp < Ln) ? tp : Ln - 1;
        float knew = g_Kv[(size_t)idxs[tk] * Hn + row];
        float thn = ths[(t + 1 < Ln) ? t + 1 : t];

        // ring store: kn[t+2] (loaded 2 iters ago); slot >= 2 away from any
        // concurrent reader at skew <= 1 -> no barrier needed before it
        if (half == 0) kns[(t + 2) & 7][pos] = Lprev;

        // ---- matvec: vp_row = M . kn_t (this thread's 64-col half) ----
        const float4* knT4 = (const float4*)(kns[t & 7] + 68 * half);
        u64t kr[32];
        u64t a0 = 0ull, a1 = 0ull;
#pragma unroll
        for (int cc = 0; cc < 16; ++cc) {
            float4 v = knT4[cc];
            kr[2 * cc] = pk2(v.x, v.y);
            kr[2 * cc + 1] = pk2(v.z, v.w);
            fma2(a0, M[2 * cc], kr[2 * cc]);
            fma2(a1, M[2 * cc + 1], kr[2 * cc + 1]);
        }
        float vph = hsum(a0) + hsum(a1);
        float vp = vph + __shfl_xor_sync(0xffffffffu, vph, 1);
        float d = kcur - vp;

        // ---- ||d||^2 block reduce (both halves hold d: 4-shuffle tree) ----
        float dsq = d * d;
        dsq += __shfl_xor_sync(0xffffffffu, dsq, 2);
        dsq += __shfl_xor_sync(0xffffffffu, dsq, 4);
        dsq += __shfl_xor_sync(0xffffffffu, dsq, 8);
        dsq += __shfl_xor_sync(0xffffffffu, dsq, 16);
        if (lane == 0) red[t & 1][w] = dsq;
        __syncthreads();   // the single barrier per step

        float4 r0 = *(const float4*)&red[t & 1][0];
        float4 r1 = *(const float4*)&red[t & 1][4];
        float dd = ((r0.x + r0.y) + (r0.z + r0.w)) + ((r1.x + r1.y) + (r1.z + r1.w));

        // ---- gate (squared compare, uniform branch) + rank-1 update ----
        if (dd >= thc) {
            float s = d * (1.0f / 2048.0f);   // (1 - alpha) * d, exact
            u64t s2 = pk2(s, s);
#pragma unroll
            for (int c = 0; c < 32; ++c) fma2(M[c], s2, kr[c]);
        }

        kcur = knx1; knx1 = knx2; knx2 = knew;
        thc = thn;
        Lprev = Lnew;
    }

    // ---- read = M @ q (raw k_2047, staged in ring slot (Ln-1)&7) ----
    __syncthreads();
    {
        const float4* q4 = (const float4*)(kns[(Ln - 1) & 7] + 68 * half);
        u64t a0 = 0ull, a1 = 0ull;
#pragma unroll
        for (int cc = 0; cc < 16; ++cc) {
            float4 v = q4[cc];
            fma2(a0, M[2 * cc], pk2(v.x, v.y));
            fma2(a1, M[2 * cc + 1], pk2(v.z, v.w));
        }
        float vph = hsum(a0) + hsum(a1);
        float rd = vph + __shfl_xor_sync(0xffffffffu, vph, 1);
        if (half == 0) g_read[b * Hn + row] = rd;
    }
}

// ------------------------- K2b: r2 = read @ rp_w^T + rp_b ------------------
__global__ void k2b(const float* __restrict__ rpw, const float* __restrict__ rpb) {
    __shared__ __align__(16) float rs[128];
    const int b = blockIdx.x, tid = threadIdx.x;
    rs[tid] = g_read[b * Hn + tid];
    __syncthreads();
    const u64t* rp = (const u64t*)rs;
    u64t acc = 0ull;
#pragma unroll 8
    for (int j2 = 0; j2 < 64; ++j2) {
        u64t wv = *(const u64t*)(rpw + tid * 128 + 2 * j2);
        fma2(acc, rp[j2], wv);
    }
    g_r2[b * Hn + tid] = hsum(acc) + rpb[tid];
}

// ------------------------- K3: out = r2 @ out_w^T + out_b ------------------
#define K3_SMEM ((64 * 128 + 64 * 130) * 4)

__global__ __launch_bounds__(256, 1)
void k3(const float* __restrict__ ow, const float* __restrict__ ob,
        float* __restrict__ out) {
    extern __shared__ float sm[];
    float* r2s = sm;             // 64 x 128
    float* ws = sm + 64 * 128;   // 64 x 130

    const int tid = threadIdx.x;
    const int v0 = blockIdx.x * 64;

    for (int i = tid; i < 64 * 32; i += 256)
        ((float4*)r2s)[i] = ((const float4*)g_r2)[i];
    for (int i = tid; i < 64 * 64; i += 256) {
        int r = i >> 6, c = i & 63;
        *(float2*)(ws + r * 130 + 2 * c) = *(const float2*)(ow + (size_t)(v0 + r) * 128 + 2 * c);
    }
    __syncthreads();

    const int vl = tid & 63;
    const int bg = tid >> 6;
    const float obv = ob[v0 + vl];

#pragma unroll 4
    for (int bi = 0; bi < 16; ++bi) {
        int bb = bg * 16 + bi;
        u64t acc = 0ull;
#pragma unroll 16
        for (int h2 = 0; h2 < 64; ++h2)
            fma2(acc, *(const u64t*)(r2s + bb * 128 + 2 * h2),
                      *(const u64t*)(ws + vl * 130 + 2 * h2));
        out[(size_t)bb * Vn + v0 + vl] = hsum(acc) + obv;
    }
}

// ------------------------- launch ------------------------------------------
extern "C" void kernel_launch(void* const* d_in, const int* in_sizes, int n_in,
                              void* d_out, int out_size) {
    (void)in_sizes; (void)n_in; (void)out_size;
    const void*  seq = d_in[0];
    const float* ew  = (const float*)d_in[1];
    const float* w1  = (const float*)d_in[2];
    const float* b1  = (const float*)d_in[3];
    const float* w2  = (const float*)d_in[4];
    const float* b2  = (const float*)d_in[5];
    const float* lng = (const float*)d_in[6];
    const float* lnb = (const float*)d_in[7];
    const float* kpw = (const float*)d_in[8];
    const float* rpw = (const float*)d_in[9];
    const float* rpb = (const float*)d_in[10];
    const float* ow  = (const float*)d_in[11];
    const float* ob  = (const float*)d_in[12];
    float* out = (float*)d_out;

    cudaFuncSetAttribute(kv1, cudaFuncAttributeMaxDynamicSharedMemorySize, KV1_SMEM);
    cudaFuncSetAttribute(kv2, cudaFuncAttributeMaxDynamicSharedMemorySize, KV2_SMEM);
    cudaFuncSetAttribute(kv3, cudaFuncAttributeMaxDynamicSharedMemorySize, KV3_SMEM);
    cudaFuncSetAttribute(k3,  cudaFuncAttributeMaxDynamicSharedMemorySize, K3_SMEM);

    k0_detect<<<1, 256>>>((const unsigned int*)seq);
    kv1<<<148, 256, KV1_SMEM>>>(ew, w1, b1);
    kv2<<<148, 256, KV2_SMEM>>>(ew, w2, b2, lng, lnb);
    kv3<<<296, 256, KV3_SMEM>>>(kpw);
    k2_scan<<<Bn, 256>>>(seq);
    k2b<<<Bn, 128>>>(rpw, rpb);
    k3<<<Vn / 64, 256, K3_SMEM>>>(ow, ob, out);
}

// round 11
// speedup vs baseline: 1.2032x; 1.0089x over previous
#include <cuda_runtime.h>
#include <cuda_bf16.h>
#include <cstdint>

// ---------------------------------------------------------------------------
// AdaptiveEMAModel. R9 committed structure (vocab tables + single-bar scan)
// + R10 micro-cuts: branchless gate (FSEL, no BSSY/BSYNC), 4-accumulator
// matvec (8-deep chains), unroll-2 main loop.
// ---------------------------------------------------------------------------

typedef unsigned long long u64t;

__device__ __forceinline__ u64t pk2(float lo, float hi) {
    u64t r;
    asm("mov.b64 %0, {%1, %2};" : "=l"(r) : "f"(lo), "f"(hi));
    return r;
}
__device__ __forceinline__ void fma2(u64t& d, u64t a, u64t b) {
    asm("fma.rn.f32x2 %0, %1, %2, %0;" : "+l"(d) : "l"(a), "l"(b));
}
__device__ __forceinline__ float2 upk(u64t v) {
    float2 f;
    asm("mov.b64 {%0, %1}, %2;" : "=f"(f.x), "=f"(f.y) : "l"(v));
    return f;
}
__device__ __forceinline__ float hsum(u64t v) {
    float2 f = upk(v);
    return f.x + f.y;
}

#define Bn   64
#define Ln   2048
#define Hn   128
#define H2n  256
#define Vn   32000
#define NTOK (Bn * Ln)

// ------------------------- global scratch ----------------------------------
__device__ __align__(16) float g_y[(size_t)Vn * H2n];      // 32.8 MB
__device__ __align__(16) float g_hln[(size_t)Vn * Hn];     // 16.4 MB
__device__ __align__(16) float g_Kv[(size_t)Vn * Hn];      // raw k per vocab
__device__ __align__(16) float g_KNv[(size_t)Vn * Hn];     // normalized k
__device__ __align__(16) float g_THv[Vn];                  // (0.4*||k||)^2
__device__ __align__(16) float g_read[Bn * Hn];
__device__ __align__(16) float g_r2[Bn * Hn];
__device__ int g_is64;

// ------------------------- K0: detect seq dtype ----------------------------
__global__ void k0_detect(const unsigned int* __restrict__ sw) {
    int t = threadIdx.x;
    int nz = (sw[2 * t + 1] != 0u) ? 1 : 0;
    nz = __syncthreads_or(nz);
    if (t == 0) g_is64 = nz ? 0 : 1;
}

// ------------------------- KV1: FFN layer 1 over vocab ---------------------
#define KV1_SMEM ((256 * 132 + 32 * 132) * 4)

__global__ __launch_bounds__(256, 1)
void kv1(const float* __restrict__ ew,
         const float* __restrict__ w1, const float* __restrict__ b1) {
    extern __shared__ float sm[];
    float* W = sm;                // 256 x 132
    float* X = sm + 256 * 132;    // 32 x 132

    const int tid = threadIdx.x;
    const int lane = tid & 31;
    const int w = tid >> 5;
    const int tg = (w & 3) * 8;
    const int ob = (w >> 2) * 4;

    for (int i = tid; i < 256 * 32; i += 256) {
        int r = i >> 5, c = i & 31;
        *(float4*)(W + r * 132 + 4 * c) = *(const float4*)(w1 + r * 128 + 4 * c);
    }
    float bb[4];
#pragma unroll
    for (int j = 0; j < 4; ++j) bb[j] = b1[lane + 32 * (ob + j)];
    __syncthreads();

    const float4* W4 = (const float4*)W;
    const float4* X4 = (const float4*)X;

    for (int tile = blockIdx.x; tile < Vn / 32; tile += gridDim.x) {
        const int v0 = tile * 32;
        for (int i = tid; i < 32 * 32; i += 256) {
            int tk = i >> 5, q = i & 31;
            *(float4*)(X + tk * 132 + 4 * q) = *(const float4*)(ew + (size_t)(v0 + tk) * 128 + 4 * q);
        }
        __syncthreads();

        u64t acc[8][4];
#pragma unroll
        for (int i = 0; i < 8; ++i)
#pragma unroll
            for (int j = 0; j < 4; ++j) acc[i][j] = 0ull;

#pragma unroll 4
        for (int hh = 0; hh < 32; ++hh) {
            u64t wl[4], wh[4];
#pragma unroll
            for (int j = 0; j < 4; ++j) {
                float4 wq = W4[(lane + 32 * (ob + j)) * 33 + hh];
                wl[j] = pk2(wq.x, wq.y);
                wh[j] = pk2(wq.z, wq.w);
            }
#pragma unroll
            for (int i = 0; i < 8; ++i) {
                float4 xq = X4[(tg + i) * 33 + hh];
                u64t xl = pk2(xq.x, xq.y), xh = pk2(xq.z, xq.w);
#pragma unroll
                for (int j = 0; j < 4; ++j) {
                    fma2(acc[i][j], xl, wl[j]);
                    fma2(acc[i][j], xh, wh[j]);
                }
            }
        }
#pragma unroll
        for (int i = 0; i < 8; ++i)
#pragma unroll
            for (int j = 0; j < 4; ++j) {
                float y = hsum(acc[i][j]) + bb[j];
                g_y[(size_t)(v0 + tg + i) * H2n + lane + 32 * (ob + j)] = fmaxf(y, 0.0f);
            }
        __syncthreads();
    }
}

// ------------------------- KV2: FFN layer 2 + residual + LN over vocab -----
#define KV2_SMEM ((128 * 260 + 64 * 260) * 4)

__global__ __launch_bounds__(256, 1)
void kv2(const float* __restrict__ ew,
         const float* __restrict__ w2, const float* __restrict__ b2,
         const float* __restrict__ lng, const float* __restrict__ lnb) {
    extern __shared__ float sm[];
    float* W = sm;                // 128 x 260
    float* Y = sm + 128 * 260;    // 64 x 260

    const int tid = threadIdx.x;
    const int lane = tid & 31;
    const int w = tid >> 5;
    const int tg = w * 8;

    for (int i = tid; i < 128 * 64; i += 256) {
        int r = i >> 6, c = i & 63;
        *(float4*)(W + r * 260 + 4 * c) = *(const float4*)(w2 + r * 256 + 4 * c);
    }
    float b2r[4], gr[4], br[4];
#pragma unroll
    for (int j = 0; j < 4; ++j) {
        b2r[j] = b2[lane + 32 * j];
        gr[j] = lng[lane + 32 * j];
        br[j] = lnb[lane + 32 * j];
    }
    __syncthreads();

    const float4* W4 = (const float4*)W;
    const float4* Y4 = (const float4*)Y;

    for (int tile = blockIdx.x; tile < Vn / 64; tile += gridDim.x) {
        const int v0 = tile * 64;
        for (int i = tid; i < 64 * 64; i += 256) {
            int tk = i >> 6, c = i & 63;
            *(float4*)(Y + tk * 260 + 4 * c) = *(const float4*)(g_y + (size_t)(v0 + tk) * H2n + 4 * c);
        }
        __syncthreads();

        u64t acc[8][4];
#pragma unroll
        for (int i = 0; i < 8; ++i)
#pragma unroll
            for (int j = 0; j < 4; ++j) acc[i][j] = 0ull;

#pragma unroll 2
        for (int oo = 0; oo < 64; ++oo) {
            u64t wl[4], wh[4];
#pragma unroll
            for (int j = 0; j < 4; ++j) {
                float4 wq = W4[(lane + 32 * j) * 65 + oo];
                wl[j] = pk2(wq.x, wq.y);
                wh[j] = pk2(wq.z, wq.w);
            }
#pragma unroll
            for (int i = 0; i < 8; ++i) {
                float4 yq = Y4[(tg + i) * 65 + oo];
                u64t yl = pk2(yq.x, yq.y), yh = pk2(yq.z, yq.w);
#pragma unroll
                for (int j = 0; j < 4; ++j) {
                    fma2(acc[i][j], yl, wl[j]);
                    fma2(acc[i][j], yh, wh[j]);
                }
            }
        }

#pragma unroll
        for (int i = 0; i < 8; ++i) {
            const size_t tok = (size_t)(v0 + tg + i);
            float x[4];
#pragma unroll
            for (int j = 0; j < 4; ++j)
                x[j] = hsum(acc[i][j]) + b2r[j] + ew[tok * 128 + lane + 32 * j];
            float s = x[0] + x[1] + x[2] + x[3];
#pragma unroll
            for (int off = 16; off; off >>= 1) s += __shfl_xor_sync(0xffffffffu, s, off);
            float mu = s * (1.0f / 128.0f);
            float vs = 0.0f;
#pragma unroll
            for (int j = 0; j < 4; ++j) { float dv = x[j] - mu; vs += dv * dv; }
#pragma unroll
            for (int off = 16; off; off >>= 1) vs += __shfl_xor_sync(0xffffffffu, vs, off);
            float den = sqrtf(vs * (1.0f / 128.0f) + 1e-5f);
#pragma unroll
            for (int j = 0; j < 4; ++j)
                g_hln[tok * Hn + lane + 32 * j] = (x[j] - mu) / den * gr[j] + br[j];
        }
        __syncthreads();
    }
}

// ------------------------- KV3: kproj + norm/kn/threshold over vocab -------
#define KV3_SMEM ((128 * 132 + 64 * 132) * 4)

__global__ __launch_bounds__(256, 1)
void kv3(const float* __restrict__ kpw) {
    extern __shared__ float sm[];
    float* W = sm;                // 128 x 132
    float* X = sm + 128 * 132;    // 64 x 132

    const int tid = threadIdx.x;
    const int lane = tid & 31;
    const int w = tid >> 5;
    const int tg = w * 8;

    for (int i = tid; i < 128 * 32; i += 256) {
        int r = i >> 5, c = i & 31;
        *(float4*)(W + r * 132 + 4 * c) = *(const float4*)(kpw + r * 128 + 4 * c);
    }
    __syncthreads();

    const float4* W4 = (const float4*)W;
    const float4* X4 = (const float4*)X;

    for (int tile = blockIdx.x; tile < Vn / 64; tile += gridDim.x) {
        const int v0 = tile * 64;
        for (int i = tid; i < 64 * 32; i += 256) {
            int tk = i >> 5, q = i & 31;
            *(float4*)(X + tk * 132 + 4 * q) = *(const float4*)(g_hln + (size_t)(v0 + tk) * Hn + 4 * q);
        }
        __syncthreads();

        u64t acc[8][4];
#pragma unroll
        for (int i = 0; i < 8; ++i)
#pragma unroll
            for (int j = 0; j < 4; ++j) acc[i][j] = 0ull;

#pragma unroll 4
        for (int hh = 0; hh < 32; ++hh) {
            u64t wl[4], wh[4];
#pragma unroll
            for (int j = 0; j < 4; ++j) {
                float4 wq = W4[(lane + 32 * j) * 33 + hh];
                wl[j] = pk2(wq.x, wq.y);
                wh[j] = pk2(wq.z, wq.w);
            }
#pragma unroll
            for (int i = 0; i < 8; ++i) {
                float4 xq = X4[(tg + i) * 33 + hh];
                u64t xl = pk2(xq.x, xq.y), xh = pk2(xq.z, xq.w);
#pragma unroll
                for (int j = 0; j < 4; ++j) {
                    fma2(acc[i][j], xl, wl[j]);
                    fma2(acc[i][j], xh, wh[j]);
                }
            }
        }
#pragma unroll
        for (int i = 0; i < 8; ++i) {
            const size_t tok = (size_t)(v0 + tg + i);
            float kv[4];
            float s = 0.0f;
#pragma unroll
            for (int j = 0; j < 4; ++j) {
                kv[j] = hsum(acc[i][j]);
                g_Kv[tok * Hn + lane + 32 * j] = kv[j];
                s += kv[j] * kv[j];
            }
#pragma unroll
            for (int off = 16; off; off >>= 1) s += __shfl_xor_sync(0xffffffffu, s, off);
            float nm = fmaxf(sqrtf(s), 1e-12f);
#pragma unroll
            for (int j = 0; j < 4; ++j)
                g_KNv[tok * Hn + lane + 32 * j] = kv[j] / nm;
            if (lane == 0) {
                float t1 = 0.4f * nm;
                g_THv[tok] = t1 * t1;
            }
        }
        __syncthreads();
    }
}

// ------------------------- K2: delta-rule scan (single bar, branchless) ----
// 64 CTAs x 256 threads. Thread pair (2r, 2r+1) owns M row r (64 cols each
// as 32 f32x2 regs). kn ring in smem written 2 steps ahead (3-step prefetch
// from the L2-hot g_KNv table); raw k + threshold via smem idx -> tables.
// Gate is branchless (FSEL); update always executes (fma with 0 when not
// firing is bit-neutral). 4 accumulators -> 8-deep fma chains.
__global__ __launch_bounds__(256, 1)
void k2_scan(const void* __restrict__ seq) {
    const int b = blockIdx.x;
    const int tid = threadIdx.x;
    const int lane = tid & 31;
    const int w = tid >> 5;
    const int row = tid >> 1;
    const int half = tid & 1;

    __shared__ int   idxs[Ln];
    __shared__ float ths[Ln];
    __shared__ __align__(16) float kns[8][136];   // kn ring, slot = t & 7
    __shared__ __align__(16) float red[2][8];

    const int is64 = g_is64;
    for (int i = tid; i < Ln; i += 256) {
        long long idx = is64 ? ((const long long*)seq)[(size_t)b * Ln + i]
                             : (long long)((const int*)seq)[(size_t)b * Ln + i];
        idxs[i] = (int)idx;
        ths[i] = g_THv[idx];
    }
    __syncthreads();

    // kn ring layout: value for column j at kns[buf][68*(j>>6) + (j&63)]
    const int pos = 68 * (row >> 6) + (row & 63);
    if (half == 0) {
        kns[0][pos] = g_KNv[(size_t)idxs[0] * Hn + row];
        kns[1][pos] = g_KNv[(size_t)idxs[1] * Hn + row];
    }
    float Lprev = g_KNv[(size_t)idxs[2] * Hn + row];       // kn[2] in flight
    float kcur = g_Kv[(size_t)idxs[0] * Hn + row];         // k_t (own row)
    float knx1 = g_Kv[(size_t)idxs[1] * Hn + row];
    float knx2 = g_Kv[(size_t)idxs[2] * Hn + row];
    float thc  = ths[0];

    u64t M[32];
#pragma unroll
    for (int c = 0; c < 32; ++c) M[c] = 0ull;
    __syncthreads();

#pragma unroll 2
    for (int t = 0; t < Ln - 1; ++t) {
        // ---- global prefetches (3 steps ahead, L2-hot tables) ----
        const int tp = t + 3;
        float Lnew = 0.0f;
        if (tp < Ln - 1)       Lnew = g_KNv[(size_t)idxs[tp] * Hn + row];
        else if (tp == Ln - 1) Lnew = g_Kv[(size_t)idxs[Ln - 1] * Hn + row];  // raw q
        const int tk = (tp < Ln) ? tp : Ln - 1;
        float knew = g_Kv[(size_t)idxs[tk] * Hn + row];
        float thn = ths[(t + 1 < Ln) ? t + 1 : t];

        // ring store: kn[t+2] (loaded 2 iters ago); slot >= 2 away from any
        // concurrent reader at skew <= 1 -> no barrier needed before it
        if (half == 0) kns[(t + 2) & 7][pos] = Lprev;

        // ---- matvec: vp_row = M . kn_t (4 accumulators, 8-deep chains) ----
        const float4* knT4 = (const float4*)(kns[t & 7] + 68 * half);
        u64t kr[32];
        u64t a0 = 0ull, a1 = 0ull, a2 = 0ull, a3 = 0ull;
#pragma unroll
        for (int cc = 0; cc < 8; ++cc) {
            float4 v0 = knT4[2 * cc];
            float4 v1 = knT4[2 * cc + 1];
            kr[4 * cc]     = pk2(v0.x, v0.y);
            kr[4 * cc + 1] = pk2(v0.z, v0.w);
            kr[4 * cc + 2] = pk2(v1.x, v1.y);
            kr[4 * cc + 3] = pk2(v1.z, v1.w);
            fma2(a0, M[4 * cc],     kr[4 * cc]);
            fma2(a1, M[4 * cc + 1], kr[4 * cc + 1]);
            fma2(a2, M[4 * cc + 2], kr[4 * cc + 2]);
            fma2(a3, M[4 * cc + 3], kr[4 * cc + 3]);
        }
        float vph = (hsum(a0) + hsum(a1)) + (hsum(a2) + hsum(a3));
        float vp = vph + __shfl_xor_sync(0xffffffffu, vph, 1);
        float d = kcur - vp;

        // ---- ||d||^2 block reduce (both halves hold d: 4-shuffle tree) ----
        float dsq = d * d;
        dsq += __shfl_xor_sync(0xffffffffu, dsq, 2);
        dsq += __shfl_xor_sync(0xffffffffu, dsq, 4);
        dsq += __shfl_xor_sync(0xffffffffu, dsq, 8);
        dsq += __shfl_xor_sync(0xffffffffu, dsq, 16);
        if (lane == 0) red[t & 1][w] = dsq;
        __syncthreads();   // the single barrier per step

        float4 r0 = *(const float4*)&red[t & 1][0];
        float4 r1 = *(const float4*)&red[t & 1][4];
        float dd = ((r0.x + r0.y) + (r0.z + r0.w)) + ((r1.x + r1.y) + (r1.z + r1.w));

        // ---- branchless gate + rank-1 update (fma w/ 0 is bit-neutral) ----
        float s = (dd >= thc) ? d * (1.0f / 2048.0f) : 0.0f;
        u64t s2 = pk2(s, s);
#pragma unroll
        for (int c = 0; c < 32; ++c) fma2(M[c], s2, kr[c]);

        kcur = knx1; knx1 = knx2; knx2 = knew;
        thc = thn;
        Lprev = Lnew;
    }

    // ---- read = M @ q (raw k_2047, staged in ring slot (Ln-1)&7) ----
    __syncthreads();
    {
        const float4* q4 = (const float4*)(kns[(Ln - 1) & 7] + 68 * half);
        u64t a0 = 0ull, a1 = 0ull;
#pragma unroll
        for (int cc = 0; cc < 16; ++cc) {
            float4 v = q4[cc];
            fma2(a0, M[2 * cc], pk2(v.x, v.y));
            fma2(a1, M[2 * cc + 1], pk2(v.z, v.w));
        }
        float vph = hsum(a0) + hsum(a1);
        float rd = vph + __shfl_xor_sync(0xffffffffu, vph, 1);
        if (half == 0) g_read[b * Hn + row] = rd;
    }
}

// ------------------------- K2b: r2 = read @ rp_w^T + rp_b ------------------
__global__ void k2b(const float* __restrict__ rpw, const float* __restrict__ rpb) {
    __shared__ __align__(16) float rs[128];
    const int b = blockIdx.x, tid = threadIdx.x;
    rs[tid] = g_read[b * Hn + tid];
    __syncthreads();
    const u64t* rp = (const u64t*)rs;
    u64t acc = 0ull;
#pragma unroll 8
    for (int j2 = 0; j2 < 64; ++j2) {
        u64t wv = *(const u64t*)(rpw + tid * 128 + 2 * j2);
        fma2(acc, rp[j2], wv);
    }
    g_r2[b * Hn + tid] = hsum(acc) + rpb[tid];
}

// ------------------------- K3: out = r2 @ out_w^T + out_b ------------------
#define K3_SMEM ((64 * 128 + 64 * 130) * 4)

__global__ __launch_bounds__(256, 1)
void k3(const float* __restrict__ ow, const float* __restrict__ ob,
        float* __restrict__ out) {
    extern __shared__ float sm[];
    float* r2s = sm;             // 64 x 128
    float* ws = sm + 64 * 128;   // 64 x 130

    const int tid = threadIdx.x;
    const int v0 = blockIdx.x * 64;

    for (int i = tid; i < 64 * 32; i += 256)
        ((float4*)r2s)[i] = ((const float4*)g_r2)[i];
    for (int i = tid; i < 64 * 64; i += 256) {
        int r = i >> 6, c = i & 63;
        *(float2*)(ws + r * 130 + 2 * c) = *(const float2*)(ow + (size_t)(v0 + r) * 128 + 2 * c);
    }
    __syncthreads();

    const int vl = tid & 63;
    const int bg = tid >> 6;
    const float obv = ob[v0 + vl];

#pragma unroll 4
    for (int bi = 0; bi < 16; ++bi) {
        int bb = bg * 16 + bi;
        u64t acc = 0ull;
#pragma unroll 16
        for (int h2 = 0; h2 < 64; ++h2)
            fma2(acc, *(const u64t*)(r2s + bb * 128 + 2 * h2),
                      *(const u64t*)(ws + vl * 130 + 2 * h2));
        out[(size_t)bb * Vn + v0 + vl] = hsum(acc) + obv;
    }
}

// ------------------------- launch ------------------------------------------
extern "C" void kernel_launch(void* const* d_in, const int* in_sizes, int n_in,
                              void* d_out, int out_size) {
    (void)in_sizes; (void)n_in; (void)out_size;
    const void*  seq = d_in[0];
    const float* ew  = (const float*)d_in[1];
    const float* w1  = (const float*)d_in[2];
    const float* b1  = (const float*)d_in[3];
    const float* w2  = (const float*)d_in[4];
    const float* b2  = (const float*)d_in[5];
    const float* lng = (const float*)d_in[6];
    const float* lnb = (const float*)d_in[7];
    const float* kpw = (const float*)d_in[8];
    const float* rpw = (const float*)d_in[9];
    const float* rpb = (const float*)d_in[10];
    const float* ow  = (const float*)d_in[11];
    const float* ob  = (const float*)d_in[12];
    float* out = (float*)d_out;

    cudaFuncSetAttribute(kv1, cudaFuncAttributeMaxDynamicSharedMemorySize, KV1_SMEM);
    cudaFuncSetAttribute(kv2, cudaFuncAttributeMaxDynamicSharedMemorySize, KV2_SMEM);
    cudaFuncSetAttribute(kv3, cudaFuncAttributeMaxDynamicSharedMemorySize, KV3_SMEM);
    cudaFuncSetAttribute(k3,  cudaFuncAttributeMaxDynamicSharedMemorySize, K3_SMEM);

    k0_detect<<<1, 256>>>((const unsigned int*)seq);
    kv1<<<148, 256, KV1_SMEM>>>(ew, w1, b1);
    kv2<<<148, 256, KV2_SMEM>>>(ew, w2, b2, lng, lnb);
    kv3<<<296, 256, KV3_SMEM>>>(kpw);
    k2_scan<<<Bn, 256>>>(seq);
    k2b<<<Bn, 128>>>(rpw, rpb);
    k3<<<Vn / 64, 256, K3_SMEM>>>(ow, ob, out);
}

// round 12
// speedup vs baseline: 1.2057x; 1.0021x over previous
#include <cuda_runtime.h>
#include <cuda_bf16.h>
#include <cstdint>

// ---------------------------------------------------------------------------
// AdaptiveEMAModel. Committed scan (R11: single-bar, branchless, vocab-table
// reads) + R12: occupancy-2 preprocess. Every preprocess GEMM stages a
// 128x132 W panel + 32x132 X tile (84.5KB) and runs 2 CTAs/SM with a
// 4-tok x 4-out register tile under __launch_bounds__(256,2).
//   kv1 -> two half-output passes; kv2 -> two half-reduction passes (partial
//   accumulator in gmem); kv3 unchanged shape. fp32 + fma.rn.f32x2 (FFMA2).
// ---------------------------------------------------------------------------

typedef unsigned long long u64t;

__device__ __forceinline__ u64t pk2(float lo, float hi) {
    u64t r;
    asm("mov.b64 %0, {%1, %2};" : "=l"(r) : "f"(lo), "f"(hi));
    return r;
}
__device__ __forceinline__ void fma2(u64t& d, u64t a, u64t b) {
    asm("fma.rn.f32x2 %0, %1, %2, %0;" : "+l"(d) : "l"(a), "l"(b));
}
__device__ __forceinline__ float2 upk(u64t v) {
    float2 f;
    asm("mov.b64 {%0, %1}, %2;" : "=f"(f.x), "=f"(f.y) : "l"(v));
    return f;
}
__device__ __forceinline__ float hsum(u64t v) {
    float2 f = upk(v);
    return f.x + f.y;
}

#define Bn   64
#define Ln   2048
#define Hn   128
#define H2n  256
#define Vn   32000
#define NTOK (Bn * Ln)

// ------------------------- global scratch ----------------------------------
__device__ __align__(16) float g_y[(size_t)Vn * H2n];      // 32.8 MB
__device__ __align__(16) float g_part[(size_t)Vn * Hn];    // 16.4 MB (ffn2 partial)
__device__ __align__(16) float g_hln[(size_t)Vn * Hn];     // 16.4 MB
__device__ __align__(16) float g_Kv[(size_t)Vn * Hn];      // raw k per vocab
__device__ __align__(16) float g_KNv[(size_t)Vn * Hn];     // normalized k
__device__ __align__(16) float g_THv[Vn];                  // (0.4*||k||)^2
__device__ __align__(16) float g_read[Bn * Hn];
__device__ __align__(16) float g_r2[Bn * Hn];
__device__ int g_is64;

// ------------------------- K0: detect seq dtype ----------------------------
__global__ void k0_detect(const unsigned int* __restrict__ sw) {
    int t = threadIdx.x;
    int nz = (sw[2 * t + 1] != 0u) ? 1 : 0;
    nz = __syncthreads_or(nz);
    if (t == 0) g_is64 = nz ? 0 : 1;
}

// ------------------------- shared GEMM core (32tok x 128out x 128red) ------
// smem: W 128 x pitch132 (67.6KB), X 32 x pitch132 (16.9KB) -> 84.5KB total,
// 2 CTAs/SM. Warp w owns tokens tg=w*4..+3; thread covers outputs
// {lane, lane+32, lane+64, lane+96}. acc[4][4] u64 = 32 regs.
#define KVT_SMEM ((128 * 132 + 32 * 132) * 4)

__device__ __forceinline__ void gemm_core(const float* __restrict__ Wsm,
                                          const float* __restrict__ Xsm,
                                          int tg, int lane, u64t acc[4][4]) {
    const float4* W4 = (const float4*)Wsm;
    const float4* X4 = (const float4*)Xsm;
#pragma unroll
    for (int i = 0; i < 4; ++i)
#pragma unroll
        for (int j = 0; j < 4; ++j) acc[i][j] = 0ull;
#pragma unroll 4
    for (int hh = 0; hh < 32; ++hh) {
        u64t wl[4], wh[4];
#pragma unroll
        for (int j = 0; j < 4; ++j) {
            float4 wq = W4[(lane + 32 * j) * 33 + hh];
            wl[j] = pk2(wq.x, wq.y);
            wh[j] = pk2(wq.z, wq.w);
        }
#pragma unroll
        for (int i = 0; i < 4; ++i) {
            float4 xq = X4[(tg + i) * 33 + hh];
            u64t xl = pk2(xq.x, xq.y), xh = pk2(xq.z, xq.w);
#pragma unroll
            for (int j = 0; j < 4; ++j) {
                fma2(acc[i][j], xl, wl[j]);
                fma2(acc[i][j], xh, wh[j]);
            }
        }
    }
}

// stage a 128x128 weight panel (row stride rstride floats) into Wsm pitch132
__device__ __forceinline__ void stage_w(float* Wsm, const float* __restrict__ src,
                                        int rstride, int tid) {
    for (int i = tid; i < 128 * 32; i += 256) {
        int r = i >> 5, c = i & 31;
        *(float4*)(Wsm + r * 132 + 4 * c) = *(const float4*)(src + (size_t)r * rstride + 4 * c);
    }
}
// stage a 32x128 activation tile (row stride rstride floats) into Xsm pitch132
__device__ __forceinline__ void stage_x(float* Xsm, const float* __restrict__ src,
                                        int rstride, int tid) {
    for (int i = tid; i < 32 * 32; i += 256) {
        int tk = i >> 5, q = i & 31;
        *(float4*)(Xsm + tk * 132 + 4 * q) = *(const float4*)(src + (size_t)tk * rstride + 4 * q);
    }
}

// ------------------------- KV1: FFN layer 1 (one output half) --------------
__global__ __launch_bounds__(256, 2)
void kv1(const float* __restrict__ ew, const float* __restrict__ w1,
         const float* __restrict__ b1, int obase) {
    extern __shared__ float sm[];
    float* W = sm;
    float* X = sm + 128 * 132;

    const int tid = threadIdx.x;
    const int lane = tid & 31;
    const int tg = (tid >> 5) * 4;

    stage_w(W, w1 + (size_t)obase * 128, 128, tid);
    float bb[4];
#pragma unroll
    for (int j = 0; j < 4; ++j) bb[j] = b1[obase + lane + 32 * j];
    __syncthreads();

    for (int tile = blockIdx.x; tile < Vn / 32; tile += gridDim.x) {
        const int v0 = tile * 32;
        stage_x(X, ew + (size_t)v0 * 128, 128, tid);
        __syncthreads();

        u64t acc[4][4];
        gemm_core(W, X, tg, lane, acc);

#pragma unroll
        for (int i = 0; i < 4; ++i)
#pragma unroll
            for (int j = 0; j < 4; ++j) {
                float y = hsum(acc[i][j]) + bb[j];
                g_y[(size_t)(v0 + tg + i) * H2n + obase + lane + 32 * j] = fmaxf(y, 0.0f);
            }
        __syncthreads();
    }
}

// ------------------------- KV2a: FFN layer 2, reduction half 0 -> partial --
__global__ __launch_bounds__(256, 2)
void kv2a(const float* __restrict__ w2) {
    extern __shared__ float sm[];
    float* W = sm;
    float* X = sm + 128 * 132;

    const int tid = threadIdx.x;
    const int lane = tid & 31;
    const int tg = (tid >> 5) * 4;

    stage_w(W, w2, 256, tid);          // w2[o][0..127]
    __syncthreads();

    for (int tile = blockIdx.x; tile < Vn / 32; tile += gridDim.x) {
        const int v0 = tile * 32;
        stage_x(X, g_y + (size_t)v0 * H2n, H2n, tid);   // Y cols 0..127
        __syncthreads();

        u64t acc[4][4];
        gemm_core(W, X, tg, lane, acc);

#pragma unroll
        for (int i = 0; i < 4; ++i)
#pragma unroll
            for (int j = 0; j < 4; ++j)
                g_part[(size_t)(v0 + tg + i) * Hn + lane + 32 * j] = hsum(acc[i][j]);
        __syncthreads();
    }
}

// ------------------------- KV2b: reduction half 1 + bias + residual + LN ---
__global__ __launch_bounds__(256, 2)
void kv2b(const float* __restrict__ ew, const float* __restrict__ w2,
          const float* __restrict__ b2,
          const float* __restrict__ lng, const float* __restrict__ lnb) {
    extern __shared__ float sm[];
    float* W = sm;
    float* X = sm + 128 * 132;

    const int tid = threadIdx.x;
    const int lane = tid & 31;
    const int tg = (tid >> 5) * 4;

    stage_w(W, w2 + 128, 256, tid);    // w2[o][128..255]
    float b2r[4], gr[4], br[4];
#pragma unroll
    for (int j = 0; j < 4; ++j) {
        b2r[j] = b2[lane + 32 * j];
        gr[j] = lng[lane + 32 * j];
        br[j] = lnb[lane + 32 * j];
    }
    __syncthreads();

    for (int tile = blockIdx.x; tile < Vn / 32; tile += gridDim.x) {
        const int v0 = tile * 32;
        stage_x(X, g_y + (size_t)v0 * H2n + 128, H2n, tid);   // Y cols 128..255
        __syncthreads();

        u64t acc[4][4];
        gemm_core(W, X, tg, lane, acc);

#pragma unroll
        for (int i = 0; i < 4; ++i) {
            const size_t tok = (size_t)(v0 + tg + i);
            float x[4];
#pragma unroll
            for (int j = 0; j < 4; ++j)
                x[j] = hsum(acc[i][j]) + g_part[tok * Hn + lane + 32 * j]
                     + b2r[j] + ew[tok * 128 + lane + 32 * j];
            float s = x[0] + x[1] + x[2] + x[3];
#pragma unroll
            for (int off = 16; off; off >>= 1) s += __shfl_xor_sync(0xffffffffu, s, off);
            float mu = s * (1.0f / 128.0f);
            float vs = 0.0f;
#pragma unroll
            for (int j = 0; j < 4; ++j) { float dv = x[j] - mu; vs += dv * dv; }
#pragma unroll
            for (int off = 16; off; off >>= 1) vs += __shfl_xor_sync(0xffffffffu, vs, off);
            float den = sqrtf(vs * (1.0f / 128.0f) + 1e-5f);
#pragma unroll
            for (int j = 0; j < 4; ++j)
                g_hln[tok * Hn + lane + 32 * j] = (x[j] - mu) / den * gr[j] + br[j];
        }
        __syncthreads();
    }
}

// ------------------------- KV3: kproj + norm/kn/threshold ------------------
__global__ __launch_bounds__(256, 2)
void kv3(const float* __restrict__ kpw) {
    extern __shared__ float sm[];
    float* W = sm;
    float* X = sm + 128 * 132;

    const int tid = threadIdx.x;
    const int lane = tid & 31;
    const int tg = (tid >> 5) * 4;

    stage_w(W, kpw, 128, tid);
    __syncthreads();

    for (int tile = blockIdx.x; tile < Vn / 32; tile += gridDim.x) {
        const int v0 = tile * 32;
        stage_x(X, g_hln + (size_t)v0 * Hn, Hn, tid);
        __syncthreads();

        u64t acc[4][4];
        gemm_core(W, X, tg, lane, acc);

#pragma unroll
        for (int i = 0; i < 4; ++i) {
            const size_t tok = (size_t)(v0 + tg + i);
            float kv[4];
            float s = 0.0f;
#pragma unroll
            for (int j = 0; j < 4; ++j) {
                kv[j] = hsum(acc[i][j]);
                g_Kv[tok * Hn + lane + 32 * j] = kv[j];
                s += kv[j] * kv[j];
            }
#pragma unroll
            for (int off = 16; off; off >>= 1) s += __shfl_xor_sync(0xffffffffu, s, off);
            float nm = fmaxf(sqrtf(s), 1e-12f);
#pragma unroll
            for (int j = 0; j < 4; ++j)
                g_KNv[tok * Hn + lane + 32 * j] = kv[j] / nm;
            if (lane == 0) {
                float t1 = 0.4f * nm;
                g_THv[tok] = t1 * t1;
            }
        }
        __syncthreads();
    }
}

// ------------------------- K2: delta-rule scan (R11 committed) -------------
__global__ __launch_bounds__(256, 1)
void k2_scan(const void* __restrict__ seq) {
    const int b = blockIdx.x;
    const int tid = threadIdx.x;
    const int lane = tid & 31;
    const int w = tid >> 5;
    const int row = tid >> 1;
    const int half = tid & 1;

    __shared__ int   idxs[Ln];
    __shared__ float ths[Ln];
    __shared__ __align__(16) float kns[8][136];   // kn ring, slot = t & 7
    __shared__ __align__(16) float red[2][8];

    const int is64 = g_is64;
    for (int i = tid; i < Ln; i += 256) {
        long long idx = is64 ? ((const long long*)seq)[(size_t)b * Ln + i]
                             : (long long)((const int*)seq)[(size_t)b * Ln + i];
        idxs[i] = (int)idx;
        ths[i] = g_THv[idx];
    }
    __syncthreads();

    const int pos = 68 * (row >> 6) + (row & 63);
    if (half == 0) {
        kns[0][pos] = g_KNv[(size_t)idxs[0] * Hn + row];
        kns[1][pos] = g_KNv[(size_t)idxs[1] * Hn + row];
    }
    float Lprev = g_KNv[(size_t)idxs[2] * Hn + row];
    float kcur = g_Kv[(size_t)idxs[0] * Hn + row];
    float knx1 = g_Kv[(size_t)idxs[1] * Hn + row];
    float knx2 = g_Kv[(size_t)idxs[2] * Hn + row];
    float thc  = ths[0];

    u64t M[32];
#pragma unroll
    for (int c = 0; c < 32; ++c) M[c] = 0ull;
    __syncthreads();

#pragma unroll 2
    for (int t = 0; t < Ln - 1; ++t) {
        const int tp = t + 3;
        float Lnew = 0.0f;
        if (tp < Ln - 1)       Lnew = g_KNv[(size_t)idxs[tp] * Hn + row];
        else if (tp == Ln - 1) Lnew = g_Kv[(size_t)idxs[Ln - 1] * Hn + row];
        const int tk = (tp < Ln) ? tp : Ln - 1;
        float knew = g_Kv[(size_t)idxs[tk] * Hn + row];
        float thn = ths[(t + 1 < Ln) ? t + 1 : t];

        if (half == 0) kns[(t + 2) & 7][pos] = Lprev;

        const float4* knT4 = (const float4*)(kns[t & 7] + 68 * half);
        u64t kr[32];
        u64t a0 = 0ull, a1 = 0ull, a2 = 0ull, a3 = 0ull;
#pragma unroll
        for (int cc = 0; cc < 8; ++cc) {
            float4 v0 = knT4[2 * cc];
            float4 v1 = knT4[2 * cc + 1];
            kr[4 * cc]     = pk2(v0.x, v0.y);
            kr[4 * cc + 1] = pk2(v0.z, v0.w);
            kr[4 * cc + 2] = pk2(v1.x, v1.y);
            kr[4 * cc + 3] = pk2(v1.z, v1.w);
            fma2(a0, M[4 * cc],     kr[4 * cc]);
            fma2(a1, M[4 * cc + 1], kr[4 * cc + 1]);
            fma2(a2, M[4 * cc + 2], kr[4 * cc + 2]);
            fma2(a3, M[4 * cc + 3], kr[4 * cc + 3]);
        }
        float vph = (hsum(a0) + hsum(a1)) + (hsum(a2) + hsum(a3));
        float vp = vph + __shfl_xor_sync(0xffffffffu, vph, 1);
        float d = kcur - vp;

        float dsq = d * d;
        dsq += __shfl_xor_sync(0xffffffffu, dsq, 2);
        dsq += __shfl_xor_sync(0xffffffffu, dsq, 4);
        dsq += __shfl_xor_sync(0xffffffffu, dsq, 8);
        dsq += __shfl_xor_sync(0xffffffffu, dsq, 16);
        if (lane == 0) red[t & 1][w] = dsq;
        __syncthreads();

        float4 r0 = *(const float4*)&red[t & 1][0];
        float4 r1 = *(const float4*)&red[t & 1][4];
        float dd = ((r0.x + r0.y) + (r0.z + r0.w)) + ((r1.x + r1.y) + (r1.z + r1.w));

        float s = (dd >= thc) ? d * (1.0f / 2048.0f) : 0.0f;
        u64t s2 = pk2(s, s);
#pragma unroll
        for (int c = 0; c < 32; ++c) fma2(M[c], s2, kr[c]);

        kcur = knx1; knx1 = knx2; knx2 = knew;
        thc = thn;
        Lprev = Lnew;
    }

    __syncthreads();
    {
        const float4* q4 = (const float4*)(kns[(Ln - 1) & 7] + 68 * half);
        u64t a0 = 0ull, a1 = 0ull;
#pragma unroll
        for (int cc = 0; cc < 16; ++cc) {
            float4 v = q4[cc];
            fma2(a0, M[2 * cc], pk2(v.x, v.y));
            fma2(a1, M[2 * cc + 1], pk2(v.z, v.w));
        }
        float vph = hsum(a0) + hsum(a1);
        float rd = vph + __shfl_xor_sync(0xffffffffu, vph, 1);
        if (half == 0) g_read[b * Hn + row] = rd;
    }
}

// ------------------------- K2b: r2 = read @ rp_w^T + rp_b ------------------
__global__ void k2b(const float* __restrict__ rpw, const float* __restrict__ rpb) {
    __shared__ __align__(16) float rs[128];
    const int b = blockIdx.x, tid = threadIdx.x;
    rs[tid] = g_read[b * Hn + tid];
    __syncthreads();
    const u64t* rp = (const u64t*)rs;
    u64t acc = 0ull;
#pragma unroll 8
    for (int j2 = 0; j2 < 64; ++j2) {
        u64t wv = *(const u64t*)(rpw + tid * 128 + 2 * j2);
        fma2(acc, rp[j2], wv);
    }
    g_r2[b * Hn + tid] = hsum(acc) + rpb[tid];
}

// ------------------------- K3: out = r2 @ out_w^T + out_b ------------------
#define K3_SMEM ((64 * 128 + 64 * 130) * 4)

__global__ __launch_bounds__(256, 1)
void k3(const float* __restrict__ ow, const float* __restrict__ ob,
        float* __restrict__ out) {
    extern __shared__ float sm[];
    float* r2s = sm;             // 64 x 128
    float* ws = sm + 64 * 128;   // 64 x 130

    const int tid = threadIdx.x;
    const int v0 = blockIdx.x * 64;

    for (int i = tid; i < 64 * 32; i += 256)
        ((float4*)r2s)[i] = ((const float4*)g_r2)[i];
    for (int i = tid; i < 64 * 64; i += 256) {
        int r = i >> 6, c = i & 63;
        *(float2*)(ws + r * 130 + 2 * c) = *(const float2*)(ow + (size_t)(v0 + r) * 128 + 2 * c);
    }
    __syncthreads();

    const int vl = tid & 63;
    const int bg = tid >> 6;
    const float obv = ob[v0 + vl];

#pragma unroll 4
    for (int bi = 0; bi < 16; ++bi) {
        int bb = bg * 16 + bi;
        u64t acc = 0ull;
#pragma unroll 16
        for (int h2 = 0; h2 < 64; ++h2)
            fma2(acc, *(const u64t*)(r2s + bb * 128 + 2 * h2),
                      *(const u64t*)(ws + vl * 130 + 2 * h2));
        out[(size_t)bb * Vn + v0 + vl] = hsum(acc) + obv;
    }
}

// ------------------------- launch ------------------------------------------
extern "C" void kernel_launch(void* const* d_in, const int* in_sizes, int n_in,
                              void* d_out, int out_size) {
    (void)in_sizes; (void)n_in; (void)out_size;
    const void*  seq = d_in[0];
    const float* ew  = (const float*)d_in[1];
    const float* w1  = (const float*)d_in[2];
    const float* b1  = (const float*)d_in[3];
    const float* w2  = (const float*)d_in[4];
    const float* b2  = (const float*)d_in[5];
    const float* lng = (const float*)d_in[6];
    const float* lnb = (const float*)d_in[7];
    const float* kpw = (const float*)d_in[8];
    const float* rpw = (const float*)d_in[9];
    const float* rpb = (const float*)d_in[10];
    const float* ow  = (const float*)d_in[11];
    const float* ob  = (const float*)d_in[12];
    float* out = (float*)d_out;

    cudaFuncSetAttribute(kv1,  cudaFuncAttributeMaxDynamicSharedMemorySize, KVT_SMEM);
    cudaFuncSetAttribute(kv2a, cudaFuncAttributeMaxDynamicSharedMemorySize, KVT_SMEM);
    cudaFuncSetAttribute(kv2b, cudaFuncAttributeMaxDynamicSharedMemorySize, KVT_SMEM);
    cudaFuncSetAttribute(kv3,  cudaFuncAttributeMaxDynamicSharedMemorySize, KVT_SMEM);
    cudaFuncSetAttribute(k3,   cudaFuncAttributeMaxDynamicSharedMemorySize, K3_SMEM);

    k0_detect<<<1, 256>>>((const unsigned int*)seq);
    kv1 <<<296, 256, KVT_SMEM>>>(ew, w1, b1, 0);
    kv1 <<<296, 256, KVT_SMEM>>>(ew, w1, b1, 128);
    kv2a<<<296, 256, KVT_SMEM>>>(w2);
    kv2b<<<296, 256, KVT_SMEM>>>(ew, w2, b2, lng, lnb);
    kv3 <<<296, 256, KVT_SMEM>>>(kpw);
    k2_scan<<<Bn, 256>>>(seq);
    k2b<<<Bn, 128>>>(rpw, rpb);
    k3<<<Vn / 64, 256, K3_SMEM>>>(ow, ob, out);
}